// round 13
// baseline (speedup 1.0000x reference)
#include <cuda_runtime.h>
#include <cuda_bf16.h>

#define FULL_MASK 0xFFFFFFFFu

// Fully group-independent variant: 4 lanes per row, 8 rows/warp, 128-thr
// blocks. NO warp-wide ballot/sync — each 4-lane group decides its row and
// stores its row itself. The common-case (cond true after chunk 0, ~80% of
// groups) store is inside the fast branch arm, so under Volta+ independent
// thread scheduling those stores issue while straggler groups are still
// waiting on gather latency, instead of the whole warp reconverging first.
__device__ __forceinline__ void store_const_row(float4* __restrict__ dist_out4,
                                                float4* __restrict__ nidx_out4,
                                                long long row, int l)
{
    long long rb = row * 16;
    const float4 z = make_float4(0.f, 0.f, 0.f, 0.f);
    #pragma unroll
    for (int t = 0; t < 4; ++t)
        dist_out4[rb + t * 4 + l] = z;
    #pragma unroll
    for (int t = 0; t < 4; ++t) {
        float4 nv = make_float4(-1.f, -1.f, -1.f, -1.f);
        if (t == 0 && l == 0) nv.x = (float)row;
        nidx_out4[rb + t * 4 + l] = nv;
    }
}

__global__ void __launch_bounds__(128)
dgb_kernel(const float4* __restrict__ dist4,
           const int*    __restrict__ nidx,
           const float*  __restrict__ score,
           float4* __restrict__ dist_out4,
           float4* __restrict__ nidx_out4,
           long long V)
{
    long long warp_id = ((long long)blockIdx.x * blockDim.x + threadIdx.x) >> 5;
    int lane = threadIdx.x & 31;
    int g = lane >> 2;                 // row group within warp: 0..7
    int l = lane & 3;                  // lane within group: 0..3
    unsigned grpmask = 0xFu << (g << 2);

    long long row = warp_id * 8 + g;
    if (row >= V) return;              // group-uniform exit

    float sv = __ldg(score + row);
    const int* nrow = nidx + row * 64;

    // ---- chunk 0: cols 1..4 (col 0 = self, never gathered) ----
    int ni0 = __ldg(nrow + 1 + l);
    bool beat0 = (ni0 >= 0) && (__ldg(score + ni0) > sv);   // strict
    bool cond0 = __any_sync(grpmask, beat0);

    if (cond0) {
        // Fast arm: stores issue immediately; under ITS they interleave
        // with other groups' straggler gathers.
        store_const_row(dist_out4, nidx_out4, row, l);
    } else {
        // ---- straggler: two 4-col chunks per ballot (R12 scheme) ----
        bool cond = false;
        #pragma unroll 1
        for (int j = 1; j < 16; j += 2) {
            int colA = (j << 2) + 1 + l;        // 5..64  (64 guarded)
            int colB = colA + 4;
            int niA = (colA < 64) ? __ldg(nrow + colA) : -1;
            int niB = (colB < 64) ? __ldg(nrow + colB) : -1;
            float vA = __ldg(score + max(niA, 0));
            float vB = __ldg(score + max(niB, 0));
            bool beat = ((niA >= 0) & (vA > sv)) |
                        ((niB >= 0) & (vB > sv));
            if (__any_sync(grpmask, beat)) { cond = true; break; }
        }

        long long rb = row * 16;
        if (cond) {
            store_const_row(dist_out4, nidx_out4, row, l);
        } else {
            const int4* nidx4 = (const int4*)nidx;
            #pragma unroll
            for (int t = 0; t < 4; ++t) {
                long long idx = rb + t * 4 + l;
                float4 dv = __ldcs(dist4 + idx);
                int4 niv = __ldcs(nidx4 + idx);
                dist_out4[idx] = dv;
                nidx_out4[idx] = make_float4((float)niv.x, (float)niv.y,
                                             (float)niv.z, (float)niv.w);
            }
        }
    }
}

extern "C" void kernel_launch(void* const* d_in, const int* in_sizes, int n_in,
                              void* d_out, int out_size)
{
    const float* dist  = (const float*)d_in[0];   // [V, 64] f32
    const int*   nidx  = (const int*)d_in[1];     // [V, 64] i32
    const float* score = (const float*)d_in[2];   // [V, 1]  f32

    long long V = in_sizes[2];                    // score element count == V

    float* out      = (float*)d_out;
    float* dist_out = out;                        // first V*64 floats
    float* nidx_out = out + V * 64;               // second V*64 (ints as f32)

    // 4 lanes per row -> V*4 threads
    long long total_threads = V * 4;
    int threads = 128;
    long long blocks = (total_threads + threads - 1) / threads;

    dgb_kernel<<<(unsigned int)blocks, threads>>>(
        (const float4*)dist, nidx, score,
        (float4*)dist_out, (float4*)nidx_out, V);
}

// round 14
// speedup vs baseline: 1.4321x; 1.4321x over previous
#include <cuda_runtime.h>
#include <cuda_bf16.h>

#define FULL_MASK 0xFFFFFFFFu

// R14: cut gather count (L1tex is the top pipe at 76%).
// 2 lanes per row, 16 rows per warp, 128-thr blocks.
// Chunk 0 probes cols 1..2 only (E[gathers/row] ~4.6 vs 6.6 at chunk=4);
// straggler rounds probe 4 cols (2 per lane, concurrent) as in R12 so the
// tail path has the same round count. Column 0 (self) never gathered.
// Write phase: warp-coherent contiguous streaming over the warp's 16 rows
// (512B per store instruction) — R13 proved divergent stores are fatal.
__global__ void __launch_bounds__(128)
dgb_kernel(const float4* __restrict__ dist4,
           const int*    __restrict__ nidx,
           const float*  __restrict__ score,
           float4* __restrict__ dist_out4,
           float4* __restrict__ nidx_out4,
           long long V)
{
    long long warp_id = ((long long)blockIdx.x * blockDim.x + threadIdx.x) >> 5;
    int lane = threadIdx.x & 31;
    int g = lane >> 1;                 // row group within warp: 0..15
    int l = lane & 1;                  // lane within group: 0..1
    unsigned grpmask = 0x3u << (g << 1);

    long long row = warp_id * 16 + g;
    bool valid = row < V;
    long long srow = valid ? row : 0;

    float sv = valid ? __ldg(score + row) : 3.0f;   // >1 => never beaten
    const int* nrow = nidx + srow * 64;

    // ---- chunk 0: cols 1..2 ----
    bool cond;
    {
        int ni = __ldg(nrow + 1 + l);
        bool beat = (ni >= 0) && (__ldg(score + ni) > sv);   // strict
        cond = __any_sync(grpmask, beat);
    }

    // ---- straggler rounds: 4 cols each (2 per lane, concurrent) ----
    if (!cond) {
        #pragma unroll 1
        for (int j = 0; j < 16; ++j) {
            int colA = 3 + (j << 2) + (l << 1);   // 3..65 (guarded)
            int colB = colA + 1;
            int niA = (colA < 64) ? __ldg(nrow + colA) : -1;
            int niB = (colB < 64) ? __ldg(nrow + colB) : -1;
            float vA = __ldg(score + max(niA, 0));
            float vB = __ldg(score + max(niB, 0));
            bool beat = ((niA >= 0) & (vA > sv)) |
                        ((niB >= 0) & (vB > sv));
            if (__any_sync(grpmask, beat)) { cond = true; break; }
        }
    }

    // Publish cond bits for all 16 rows of this warp (bit at lane 2g).
    unsigned bal = __ballot_sync(FULL_MASK, cond);

    // ---- write phase: contiguous streaming over the warp's 16 rows ----
    long long warp_row0 = warp_id * 16;
    long long gbase = warp_row0 * 16;  // float4 index of region start
    const int4* nidx4 = (const int4*)nidx;

    #pragma unroll
    for (int t = 0; t < 8; ++t) {
        int vec = t * 32 + lane;       // 0..255 within warp region
        int row_local = vec >> 4;      // 0..15
        int within = vec & 15;         // float4 within row
        long long rr = warp_row0 + row_local;
        if (rr >= V) continue;
        long long idx = gbase + vec;

        bool c = (bal >> (row_local << 1)) & 1u;

        float4 dv, nv;
        if (c) {
            dv = make_float4(0.f, 0.f, 0.f, 0.f);
            nv = make_float4(-1.f, -1.f, -1.f, -1.f);
            if (within == 0) nv.x = (float)rr;
        } else {
            dv = __ldcs(dist4 + idx);
            int4 niv = __ldcs(nidx4 + idx);
            nv = make_float4((float)niv.x, (float)niv.y,
                             (float)niv.z, (float)niv.w);
        }
        dist_out4[idx] = dv;
        nidx_out4[idx] = nv;
    }
}

extern "C" void kernel_launch(void* const* d_in, const int* in_sizes, int n_in,
                              void* d_out, int out_size)
{
    const float* dist  = (const float*)d_in[0];   // [V, 64] f32
    const int*   nidx  = (const int*)d_in[1];     // [V, 64] i32
    const float* score = (const float*)d_in[2];   // [V, 1]  f32

    long long V = in_sizes[2];                    // score element count == V

    float* out      = (float*)d_out;
    float* dist_out = out;                        // first V*64 floats
    float* nidx_out = out + V * 64;               // second V*64 (ints as f32)

    // 2 lanes per row -> V*2 threads
    long long total_threads = V * 2;
    int threads = 128;
    long long blocks = (total_threads + threads - 1) / threads;

    dgb_kernel<<<(unsigned int)blocks, threads>>>(
        (const float4*)dist, nidx, score,
        (float4*)dist_out, (float4*)nidx_out, V);
}

// round 15
// speedup vs baseline: 1.4884x; 1.0394x over previous
#include <cuda_runtime.h>
#include <cuda_bf16.h>

#define FULL_MASK 0xFFFFFFFFu

// R12 structure (best: 106.6us) with two trims:
//  (a) all-32-bit index arithmetic (R12 showed ALU pipe at 43% from int64
//      IMAD chains; every index here fits in 32 bits: max float4 idx = 16M),
//  (b) write phase issues all 4 dist stores, then all 4 nidx stores, giving
//      2KB contiguous bursts per output stream instead of interleaving two
//      regions 256MB apart.
// Decide: 4 lanes/row, 8 rows/warp, chunk 0 = cols 1..4, straggler rounds
// 2x4 cols per ballot, strict '>' matches reference diff < 0.
__global__ void __launch_bounds__(128)
dgb_kernel(const float4* __restrict__ dist4,
           const int*    __restrict__ nidx,
           const float*  __restrict__ score,
           float4* __restrict__ dist_out4,
           float4* __restrict__ nidx_out4,
           int V)
{
    int warp_id = (int)(((unsigned)blockIdx.x * blockDim.x + threadIdx.x) >> 5);
    int lane = threadIdx.x & 31;
    int g = lane >> 2;                 // row group within warp: 0..7
    int l = lane & 3;                  // lane within group: 0..3
    unsigned grpmask = 0xFu << (g << 2);

    int row = warp_id * 8 + g;
    bool valid = row < V;
    int srow = valid ? row : 0;

    float sv = valid ? __ldg(score + row) : 3.0f;   // >1 => never beaten
    const int* nrow = nidx + (unsigned)srow * 64u;

    // ---- chunk 0: cols 1..4 (col 0 = self, never gathered) ----
    bool cond;
    {
        int ni = __ldg(nrow + 1 + l);
        bool beat = (ni >= 0) && (__ldg(score + ni) > sv);   // strict
        cond = __any_sync(grpmask, beat);
    }

    // ---- straggler loop: two 4-col chunks per ballot ----
    if (!cond) {
        #pragma unroll 1
        for (int j = 1; j < 16; j += 2) {
            int colA = (j << 2) + 1 + l;        // 5..64  (64 guarded)
            int colB = colA + 4;
            int niA = (colA < 64) ? __ldg(nrow + colA) : -1;
            int niB = (colB < 64) ? __ldg(nrow + colB) : -1;
            float vA = __ldg(score + max(niA, 0));
            float vB = __ldg(score + max(niB, 0));
            bool beat = ((niA >= 0) & (vA > sv)) |
                        ((niB >= 0) & (vB > sv));
            if (__any_sync(grpmask, beat)) { cond = true; break; }
        }
    }

    // Publish cond bits for all 8 rows of this warp (bit at lane g*4).
    unsigned bal = __ballot_sync(FULL_MASK, cond);

    // ---- write phase: contiguous streaming over the warp's 8 rows ----
    int warp_row0 = warp_id * 8;
    unsigned gbase = (unsigned)warp_row0 * 16u;   // float4 idx (max 16M)
    const int4* nidx4 = (const int4*)nidx;

    // dist stores first: 4 x 512B contiguous bursts to one region
    #pragma unroll
    for (int t = 0; t < 4; ++t) {
        int vec = t * 32 + lane;       // 0..127 within warp region
        int row_local = vec >> 4;      // 0..7
        int rr = warp_row0 + row_local;
        if (rr >= V) continue;
        unsigned idx = gbase + (unsigned)vec;
        bool c = (bal >> (row_local << 2)) & 1u;
        float4 dv = c ? make_float4(0.f, 0.f, 0.f, 0.f)
                      : __ldcs(dist4 + idx);
        dist_out4[idx] = dv;
    }

    // then nidx stores: 4 x 512B contiguous bursts to the other region
    #pragma unroll
    for (int t = 0; t < 4; ++t) {
        int vec = t * 32 + lane;
        int row_local = vec >> 4;
        int within = vec & 15;
        int rr = warp_row0 + row_local;
        if (rr >= V) continue;
        unsigned idx = gbase + (unsigned)vec;
        bool c = (bal >> (row_local << 2)) & 1u;

        float4 nv;
        if (c) {
            nv = make_float4(-1.f, -1.f, -1.f, -1.f);
            if (within == 0) nv.x = (float)rr;
        } else {
            int4 niv = __ldcs(nidx4 + idx);
            nv = make_float4((float)niv.x, (float)niv.y,
                             (float)niv.z, (float)niv.w);
        }
        nidx_out4[idx] = nv;
    }
}

extern "C" void kernel_launch(void* const* d_in, const int* in_sizes, int n_in,
                              void* d_out, int out_size)
{
    const float* dist  = (const float*)d_in[0];   // [V, 64] f32
    const int*   nidx  = (const int*)d_in[1];     // [V, 64] i32
    const float* score = (const float*)d_in[2];   // [V, 1]  f32

    int V = in_sizes[2];                          // score element count == V

    float* out      = (float*)d_out;
    float* dist_out = out;                        // first V*64 floats
    float* nidx_out = out + (long long)V * 64;    // second V*64 (ints as f32)

    // 4 lanes per row -> V*4 threads
    long long total_threads = (long long)V * 4;
    int threads = 128;
    long long blocks = (total_threads + threads - 1) / threads;

    dgb_kernel<<<(unsigned int)blocks, threads>>>(
        (const float4*)dist, nidx, score,
        (float4*)dist_out, (float4*)nidx_out, V);
}